// round 9
// baseline (speedup 1.0000x reference)
#include <cuda_runtime.h>
#include <cuda_fp16.h>
#include <cstdint>

#define BB   8
#define MM   4096
#define NN   16384
#define HH   128
#define WW   128
#define BN   (BB*NN)
#define TAUF 0.01f
#define EPSF 1e-8f
#define ITERS 100

#define KC1    8            // phase-1 K chunks (16384/8 = 2048)
#define KC2    2            // phase-2 K chunks (4096/2 = 2048)
#define KCHUNK 2048
#define NSTEPS 32           // KCHUNK / 64 cols per stage

// smem: 4 slots x 24KB; slot = A[4 warps][4KB] + B[4 warps][2KB]
#define SLOT_BYTES 24576
#define SM_TOTAL   (4 * SLOT_BYTES)

// ---------------- device state (no allocations allowed) ----------------
__device__ __half g_Ah [(size_t)MM * NN];     // A fp16 row-major [i][j]
__device__ __half g_AhT[(size_t)MM * NN];     // A^T fp16 [j][i]
__device__ float  g_x[BN];
__device__ float  g_xbar[BN];
__device__ float  g_t[BN];
__device__ float  g_yb[2][2][BN];
__device__ __half g_t16[(size_t)16 * NN];     // rows 0-7 = hi(t), 8-15 = lo(t)*2048
__device__ __half g_r16[(size_t)16 * MM];     // rows 0-7 = hi(r), 8-15 = lo(r)*2048
__device__ float  g_rpart[(size_t)KC1 * MM * 8];   // phase-1 partials [kc][i][b]
__device__ float  g_gpart[(size_t)KC2 * NN * 8];   // phase-2 partials [kc][j][b]

// ---------------- helpers ----------------
#define SWZ(o) ((o) ^ (((o) >> 3) & 0x70))

#define CP16(DST, SRC) \
    asm volatile("cp.async.cg.shared.global [%0], [%1], 16;" :: "r"(DST), "l"(SRC))
#define CP_COMMIT() asm volatile("cp.async.commit_group;" ::: "memory")
#define CP_WAIT2()  asm volatile("cp.async.wait_group 2;"  ::: "memory")

#define LDM_X4(R0, R1, R2, R3, ADDR)                                          \
    asm volatile("ldmatrix.sync.aligned.m8n8.x4.shared.b16 {%0,%1,%2,%3}, [%4];" \
                 : "=r"(R0), "=r"(R1), "=r"(R2), "=r"(R3) : "r"(ADDR))

#define MMA16816(C, A0, A1, A2, A3, B0, B1)                                   \
    asm volatile("mma.sync.aligned.m16n8k16.row.col.f32.f16.f16.f32 "         \
                 "{%0,%1,%2,%3}, {%4,%5,%6,%7}, {%8,%9}, {%0,%1,%2,%3};"      \
                 : "+f"((C)[0]), "+f"((C)[1]), "+f"((C)[2]), "+f"((C)[3])     \
                 : "r"(A0), "r"(A1), "r"(A2), "r"(A3), "r"(B0), "r"(B1))

// ---------------- setup: A fp32 -> fp16 + fp16 transpose (one-time) ----------
__global__ void k_setup(const float* __restrict__ A) {
    __shared__ __half tile[32][33];
    int j0 = blockIdx.x * 32, i0 = blockIdx.y * 32;
    int tx = threadIdx.x, ty = threadIdx.y;          // (32, 8)
#pragma unroll
    for (int q = 0; q < 4; q++) {
        int il = ty + q * 8;
        float v = A[(size_t)(i0 + il) * NN + j0 + tx];
        __half h = __float2half_rn(v);
        g_Ah[(size_t)(i0 + il) * NN + j0 + tx] = h;
        tile[il][tx] = h;
    }
    __syncthreads();
#pragma unroll
    for (int q = 0; q < 4; q++) {
        int jl = ty + q * 8;
        g_AhT[(size_t)(j0 + jl) * MM + i0 + tx] = tile[tx][jl];
    }
}

// ---------------- zero init ----------------
__global__ void k_zero() {
    int idx = blockIdx.x * blockDim.x + threadIdx.x;
    if (idx < BN) {
        g_x[idx] = 0.f; g_xbar[idx] = 0.f;
        g_yb[0][0][idx] = 0.f; g_yb[0][1][idx] = 0.f;
    }
}

// ---------------- TV stencil + t16 hi/lo emit ----------------
__global__ void k_tv(int bi) {
    int idx = blockIdx.x * blockDim.x + threadIdx.x;
    if (idx >= BN) return;
    int p = idx & (NN - 1);
    int i = p >> 7;
    int j = p & 127;

    const float* yx = g_yb[bi][0];
    const float* yy = g_yb[bi][1];
    float*       oyx = g_yb[bi ^ 1][0];
    float*       oyy = g_yb[bi ^ 1][1];

    float yxv = yx[idx];
    float yyv = yy[idx];

    float dx = (j > 0) ? (yxv - yx[idx - 1])  : 0.f;
    float dy = (i > 0) ? (yyv - yy[idx - WW]) : 0.f;
    float t = g_x[idx] - TAUF * (dx + dy);
    g_t[idx] = t;

    __half hi = __float2half_rn(t);
    float  lo = (t - __half2float(hi)) * 2048.f;
    g_t16[idx] = hi;
    g_t16[(size_t)BN + idx] = __float2half_rn(lo);

    float xb = g_xbar[idx];
    float gx = (j < WW - 1) ? (xb - g_xbar[idx + 1])  : 0.f;
    float gy = (i < HH - 1) ? (xb - g_xbar[idx + WW]) : 0.f;

    float nyx = yxv + TAUF * gx;
    float nyy = yyv + TAUF * gy;
    float denom = fmaxf(fabsf(nyx), fabsf(nyy)) + EPSF;
    float inv = 1.f / denom;
    oyx[idx] = nyx * inv;
    oyy[idx] = nyy * inv;
}

// ---------------- unified HMMA GEMV kernel -----------------------------------
// phase 0: D[i,b16] += A[i,k]  * t16[b16,k]  (g_Ah,  K=NN, M=MM, grid (32,KC1))
// phase 1: D[j,b16] += AT[j,k] * r16[b16,k]  (g_AhT, K=MM, M=NN, grid (128,KC2))
// CTA: 128 rows x 2048-col K chunk = 32 stages of 64 cols.
// FULLY WARP-PRIVATE pipeline: warp w loads its own A rows (w*32..+32) and its
// own B replica each stage; wait_group + syncwarp only, no CTA barriers.
__global__ __launch_bounds__(128) void k_mma(int phase) {
    extern __shared__ char sm[];
    unsigned smb = (unsigned)__cvta_generic_to_shared(sm);
    int tid = threadIdx.x, wid = tid >> 5, lane = tid & 31;

    const __half* Aop = phase ? g_AhT : g_Ah;
    const __half* Bop = phase ? g_r16 : g_t16;
    float*        outp = phase ? g_gpart : g_rpart;
    const int Ktot = phase ? MM : NN;
    const int Mtot = phase ? NN : MM;

    int r0 = blockIdx.x * 128;
    int k0 = blockIdx.y * KCHUNK;

    // per-warp smem regions (within a slot)
    unsigned aw_off = (unsigned)(wid * 4096);           // A: 32 rows x 128 B
    unsigned bw_off = (unsigned)(16384 + wid * 2048);   // B: 16 rows x 128 B

    const __half* asrc_base = Aop + (size_t)(r0 + wid * 32) * Ktot + k0;
    const __half* bsrc_base = Bop + k0;

    // ---- warp-private stage fill: 12 x 16B cp.async per lane ----
    auto fill = [&](int s) {
        unsigned slotb = smb + (unsigned)((s & 3) * SLOT_BYTES);
        const __half* asrc = asrc_base + s * 64;
#pragma unroll
        for (int q = 0; q < 8; q++) {
            int c = lane + q * 32;           // 256 16B chunks: row 0..31, c16 0..7
            int row = c >> 3, c16 = c & 7;
            unsigned off = (unsigned)(row * 128 + c16 * 16);
            CP16(slotb + aw_off + SWZ(off), asrc + (size_t)row * Ktot + c16 * 8);
        }
        const __half* bsrc = bsrc_base + s * 64;
#pragma unroll
        for (int q = 0; q < 4; q++) {
            int c = lane + q * 32;           // 128 chunks: row 0..15, c16 0..7
            int row = c >> 3, c16 = c & 7;
            unsigned off = (unsigned)(row * 128 + c16 * 16);
            CP16(slotb + bw_off + SWZ(off), bsrc + (size_t)row * Ktot + c16 * 8);
        }
        CP_COMMIT();
    };

    float c[2][2][4];
#pragma unroll
    for (int mt = 0; mt < 2; mt++)
#pragma unroll
        for (int nt = 0; nt < 2; nt++)
#pragma unroll
            for (int q = 0; q < 4; q++) c[mt][nt][q] = 0.f;

    fill(0); fill(1); fill(2);

    int l8 = lane & 7;
    int lq = lane >> 3;                  // ldmatrix quadrant 0..3

    for (int s = 0; s < NSTEPS; s++) {
        CP_WAIT2();
        __syncwarp();                    // cross-lane visibility of this warp's fills

        int ns = s + 3;
        if (ns < NSTEPS) { fill(ns); } else { CP_COMMIT(); }

        unsigned slotb = smb + (unsigned)((s & 3) * SLOT_BYTES);
        unsigned abase = slotb + aw_off;
        unsigned bbase = slotb + bw_off;

#pragma unroll
        for (int kk = 0; kk < 4; kk++) {
            // B frags: [n0-7,k0-7],[n0-7,k8-15],[n8-15,k0-7],[n8-15,k8-15]
            unsigned brow = (lq >> 1) * 8 + l8;
            unsigned bcol = kk * 32 + (lq & 1) * 16;
            unsigned b0, b1, b2, b3;
            LDM_X4(b0, b1, b2, b3, bbase + SWZ(brow * 128 + bcol));

#pragma unroll
            for (int mt = 0; mt < 2; mt++) {
                // A frags (local rows 0..31): [r0-7,k0-7],[r8-15,k0-7],[r0-7,k8-15],[r8-15,k8-15]
                unsigned arow = mt * 16 + (lq & 1) * 8 + l8;
                unsigned acol = kk * 32 + (lq >> 1) * 16;
                unsigned a0, a1, a2, a3;
                LDM_X4(a0, a1, a2, a3, abase + SWZ(arow * 128 + acol));

                MMA16816(c[mt][0], a0, a1, a2, a3, b0, b1);   // hi batches
                MMA16816(c[mt][1], a0, a1, a2, a3, b2, b3);   // lo batches
            }
        }
    }

    // ---- epilogue: fold hi + lo/2048, write partials ----
    int g = lane >> 2, t4 = lane & 3;
#pragma unroll
    for (int mt = 0; mt < 2; mt++) {
        int row = r0 + wid * 32 + mt * 16 + g;
        float* d0 = outp + ((size_t)blockIdx.y * Mtot + row) * 8 + t4 * 2;
        float* d1 = outp + ((size_t)blockIdx.y * Mtot + row + 8) * 8 + t4 * 2;
        const float is = 1.f / 2048.f;
        *reinterpret_cast<float2*>(d0) = make_float2(
            c[mt][0][0] + c[mt][1][0] * is, c[mt][0][1] + c[mt][1][1] * is);
        *reinterpret_cast<float2*>(d1) = make_float2(
            c[mt][0][2] + c[mt][1][2] * is, c[mt][0][3] + c[mt][1][3] * is);
    }
}

// ---------------- r prep: r = sum(rpart) - meas -> hi/lo fp16 ----------------
__global__ void k_rprep(const float* __restrict__ meas) {
    int idx = blockIdx.x * blockDim.x + threadIdx.x;   // 32768
    int i = idx >> 3, b = idx & 7;
    float v = -meas[b * MM + i];
#pragma unroll
    for (int kc = 0; kc < KC1; kc++)
        v += g_rpart[((size_t)kc * MM + i) * 8 + b];
    __half hi = __float2half_rn(v);
    float  lo = (v - __half2float(hi)) * 2048.f;
    g_r16[(size_t)b * MM + i] = hi;
    g_r16[(size_t)(b + 8) * MM + i] = __float2half_rn(lo);
}

// ---------------- finish: x = t - grad ; xbar = 2x - xbar_old ----------------
__global__ void k_fin() {
    int idx = blockIdx.x * blockDim.x + threadIdx.x;
    if (idx >= BN) return;
    int b = idx >> 14;
    int j = idx & (NN - 1);
    float s = 0.f;
#pragma unroll
    for (int kc = 0; kc < KC2; kc++)
        s += g_gpart[((size_t)kc * NN + j) * 8 + b];
    float xn = g_t[idx] - s;
    float xbo = g_xbar[idx];
    g_x[idx] = xn;
    g_xbar[idx] = 2.f * xn - xbo;
}

// ---------------- output copy ----------------
__global__ void k_copy(float* __restrict__ out) {
    int idx = blockIdx.x * blockDim.x + threadIdx.x;
    if (idx < BN) out[idx] = g_x[idx];
}

// ---------------- launch ----------------
extern "C" void kernel_launch(void* const* d_in, const int* in_sizes, int n_in,
                              void* d_out, int out_size) {
    const float* meas = (const float*)d_in[0];
    const float* A    = (const float*)d_in[1];
    if (n_in >= 2 && in_sizes[0] != BB * MM) {
        meas = (const float*)d_in[1];
        A    = (const float*)d_in[0];
    }
    float* out = (float*)d_out;

    cudaFuncSetAttribute(k_mma, cudaFuncAttributeMaxDynamicSharedMemorySize, SM_TOTAL);

    k_setup<<<dim3(NN / 32, MM / 32), dim3(32, 8)>>>(A);
    k_zero<<<BN / 256, 256>>>();

    for (int it = 0; it < ITERS; it++) {
        int bi = it & 1;
        k_tv<<<BN / 256, 256>>>(bi);
        k_mma<<<dim3(MM / 128, KC1), 128, SM_TOTAL>>>(0);
        k_rprep<<<(MM * 8) / 256, 256>>>(meas);
        k_mma<<<dim3(NN / 128, KC2), 128, SM_TOTAL>>>(1);
        k_fin<<<BN / 256, 256>>>();
    }
    k_copy<<<BN / 256, 256>>>(out);
}

// round 10
// speedup vs baseline: 1.0684x; 1.0684x over previous
#include <cuda_runtime.h>
#include <cuda_fp16.h>
#include <cstdint>

#define BB   8
#define MM   4096
#define NN   16384
#define HH   128
#define WW   128
#define BN   (BB*NN)
#define TAUF 0.01f
#define EPSF 1e-8f
#define ITERS 100

#define KC1    8            // phase-1 K chunks (16384/8 = 2048)
#define KC2    2            // phase-2 K chunks (4096/2 = 2048)
#define KCHUNK 2048
#define NSTEPS 16           // KCHUNK / 128 cols per stage

// smem: 3 slots x 36KB; slot = A[2 subtiles][16KB] + B[2 subtiles][2KB]
#define SLOT_A0   0
#define SLOT_A1   16384
#define SLOT_B0   32768
#define SLOT_B1   34816
#define SLOT_BYTES 36864
#define SM_TOTAL  (3 * SLOT_BYTES)     // 108 KB

// ---------------- device state (no allocations allowed) ----------------
__device__ __half g_Ah [(size_t)MM * NN];     // A fp16 row-major [i][j]
__device__ __half g_AhT[(size_t)MM * NN];     // A^T fp16 [j][i]
__device__ float  g_x[BN];
__device__ float  g_xbar[BN];
__device__ float  g_t[BN];
__device__ float  g_yb[2][2][BN];
__device__ __half g_t16[(size_t)16 * NN];     // rows 0-7 = hi(t), 8-15 = lo(t)*2048
__device__ __half g_r16[(size_t)16 * MM];     // rows 0-7 = hi(r), 8-15 = lo(r)*2048
__device__ float  g_rpart[(size_t)KC1 * MM * 8];   // phase-1 partials [kc][i][b]
__device__ float  g_gpart[(size_t)KC2 * NN * 8];   // phase-2 partials [kc][j][b]

// ---------------- helpers ----------------
#define SWZ(o) ((o) ^ (((o) >> 3) & 0x70))

#define CP16(DST, SRC) \
    asm volatile("cp.async.cg.shared.global [%0], [%1], 16;" :: "r"(DST), "l"(SRC))
#define CP_COMMIT() asm volatile("cp.async.commit_group;" ::: "memory")
#define CP_WAIT1()  asm volatile("cp.async.wait_group 1;"  ::: "memory")

#define LDM_X4(R0, R1, R2, R3, ADDR)                                          \
    asm volatile("ldmatrix.sync.aligned.m8n8.x4.shared.b16 {%0,%1,%2,%3}, [%4];" \
                 : "=r"(R0), "=r"(R1), "=r"(R2), "=r"(R3) : "r"(ADDR))

#define MMA16816(C, A0, A1, A2, A3, B0, B1)                                   \
    asm volatile("mma.sync.aligned.m16n8k16.row.col.f32.f16.f16.f32 "         \
                 "{%0,%1,%2,%3}, {%4,%5,%6,%7}, {%8,%9}, {%0,%1,%2,%3};"      \
                 : "+f"((C)[0]), "+f"((C)[1]), "+f"((C)[2]), "+f"((C)[3])     \
                 : "r"(A0), "r"(A1), "r"(A2), "r"(A3), "r"(B0), "r"(B1))

// ---------------- setup: A fp32 -> fp16 + fp16 transpose (one-time) ----------
__global__ void k_setup(const float* __restrict__ A) {
    __shared__ __half tile[32][33];
    int j0 = blockIdx.x * 32, i0 = blockIdx.y * 32;
    int tx = threadIdx.x, ty = threadIdx.y;          // (32, 8)
#pragma unroll
    for (int q = 0; q < 4; q++) {
        int il = ty + q * 8;
        float v = A[(size_t)(i0 + il) * NN + j0 + tx];
        __half h = __float2half_rn(v);
        g_Ah[(size_t)(i0 + il) * NN + j0 + tx] = h;
        tile[il][tx] = h;
    }
    __syncthreads();
#pragma unroll
    for (int q = 0; q < 4; q++) {
        int jl = ty + q * 8;
        g_AhT[(size_t)(j0 + jl) * MM + i0 + tx] = tile[tx][jl];
    }
}

// ---------------- zero init ----------------
__global__ void k_zero() {
    int idx = blockIdx.x * blockDim.x + threadIdx.x;
    if (idx < BN) {
        g_x[idx] = 0.f; g_xbar[idx] = 0.f;
        g_yb[0][0][idx] = 0.f; g_yb[0][1][idx] = 0.f;
    }
}

// ---------------- TV stencil + t16 hi/lo emit ----------------
__global__ void k_tv(int bi) {
    int idx = blockIdx.x * blockDim.x + threadIdx.x;
    if (idx >= BN) return;
    int p = idx & (NN - 1);
    int i = p >> 7;
    int j = p & 127;

    const float* yx = g_yb[bi][0];
    const float* yy = g_yb[bi][1];
    float*       oyx = g_yb[bi ^ 1][0];
    float*       oyy = g_yb[bi ^ 1][1];

    float yxv = yx[idx];
    float yyv = yy[idx];

    float dx = (j > 0) ? (yxv - yx[idx - 1])  : 0.f;
    float dy = (i > 0) ? (yyv - yy[idx - WW]) : 0.f;
    float t = g_x[idx] - TAUF * (dx + dy);
    g_t[idx] = t;

    __half hi = __float2half_rn(t);
    float  lo = (t - __half2float(hi)) * 2048.f;
    g_t16[idx] = hi;
    g_t16[(size_t)BN + idx] = __float2half_rn(lo);

    float xb = g_xbar[idx];
    float gx = (j < WW - 1) ? (xb - g_xbar[idx + 1])  : 0.f;
    float gy = (i < HH - 1) ? (xb - g_xbar[idx + WW]) : 0.f;

    float nyx = yxv + TAUF * gx;
    float nyy = yyv + TAUF * gy;
    float denom = fmaxf(fabsf(nyx), fabsf(nyy)) + EPSF;
    float inv = 1.f / denom;
    oyx[idx] = nyx * inv;
    oyy[idx] = nyy * inv;
}

// ---------------- unified HMMA GEMV kernel -----------------------------------
// phase 0: D[i,b16] += A[i,k]  * t16[b16,k]  (g_Ah,  K=NN, M=MM, grid (32,KC1))
// phase 1: D[j,b16] += AT[j,k] * r16[b16,k]  (g_AhT, K=MM, M=NN, grid (128,KC2))
// CTA: 128 rows x 2048-col K chunk = 16 stages of 128 cols.
// Stage = TWO 64-col sub-tiles (R8 layout each): A 2x16KB SW128, B 2x2KB SW128.
// 3-slot ring, cp.async wait_group 1, one __syncthreads per stage.
__global__ __launch_bounds__(128) void k_mma(int phase) {
    extern __shared__ char sm[];
    unsigned smb = (unsigned)__cvta_generic_to_shared(sm);
    int tid = threadIdx.x, wid = tid >> 5, lane = tid & 31;

    const __half* Aop = phase ? g_AhT : g_Ah;
    const __half* Bop = phase ? g_r16 : g_t16;
    float*        outp = phase ? g_gpart : g_rpart;
    const int Ktot = phase ? MM : NN;
    const int Mtot = phase ? NN : MM;

    int r0 = blockIdx.x * 128;
    int k0 = blockIdx.y * KCHUNK;

    // ---- stage fill: 2 sub-tiles, 18 x 16B cp.async per thread, one commit ----
    auto fill = [&](int s) {
        unsigned slotb = smb + (unsigned)((s % 3) * SLOT_BYTES);
#pragma unroll
        for (int half = 0; half < 2; half++) {
            const __half* asrc = Aop + (size_t)r0 * Ktot + k0 + s * 128 + half * 64;
            unsigned abase = slotb + (half ? SLOT_A1 : SLOT_A0);
#pragma unroll
            for (int q = 0; q < 8; q++) {
                int c = tid + q * 128;            // 1024 chunks: row 0..127, c16 0..7
                int row = c >> 3, c16 = c & 7;
                unsigned off = (unsigned)(row * 128 + c16 * 16);
                CP16(abase + SWZ(off), asrc + (size_t)row * Ktot + c16 * 8);
            }
            const __half* bsrc = Bop + k0 + s * 128 + half * 64;
            int brow = tid >> 3, bc16 = tid & 7;  // 128 chunks: row 0..15, c16 0..7
            unsigned boff = (unsigned)(brow * 128 + bc16 * 16);
            CP16(slotb + (half ? SLOT_B1 : SLOT_B0) + SWZ(boff),
                 bsrc + (size_t)brow * Ktot + bc16 * 8);
        }
        CP_COMMIT();
    };

    float c[2][2][4];
#pragma unroll
    for (int mt = 0; mt < 2; mt++)
#pragma unroll
        for (int nt = 0; nt < 2; nt++)
#pragma unroll
            for (int q = 0; q < 4; q++) c[mt][nt][q] = 0.f;

    fill(0); fill(1);

    int l8 = lane & 7;
    int lq = lane >> 3;                  // ldmatrix quadrant 0..3

    for (int s = 0; s < NSTEPS; s++) {
        CP_WAIT1();
        __syncthreads();                 // stage s visible; stage s-1 consumption done

        int ns = s + 2;
        if (ns < NSTEPS) { fill(ns); } else { CP_COMMIT(); }

        unsigned slotb = smb + (unsigned)((s % 3) * SLOT_BYTES);

#pragma unroll
        for (int kk = 0; kk < 8; kk++) {
            unsigned abase = slotb + ((kk < 4) ? SLOT_A0 : SLOT_A1);
            unsigned bbase = slotb + ((kk < 4) ? SLOT_B0 : SLOT_B1);
            int k4 = kk & 3;

            // B frags: [n0-7,k0-7],[n0-7,k8-15],[n8-15,k0-7],[n8-15,k8-15]
            unsigned brow = (lq >> 1) * 8 + l8;
            unsigned bcol = k4 * 32 + (lq & 1) * 16;
            unsigned b0, b1, b2, b3;
            LDM_X4(b0, b1, b2, b3, bbase + SWZ(brow * 128 + bcol));

#pragma unroll
            for (int mt = 0; mt < 2; mt++) {
                unsigned arow = wid * 32 + mt * 16 + (lq & 1) * 8 + l8;
                unsigned acol = k4 * 32 + (lq >> 1) * 16;
                unsigned a0, a1, a2, a3;
                LDM_X4(a0, a1, a2, a3, abase + SWZ(arow * 128 + acol));

                MMA16816(c[mt][0], a0, a1, a2, a3, b0, b1);   // hi batches
                MMA16816(c[mt][1], a0, a1, a2, a3, b2, b3);   // lo batches
            }
        }
    }

    // ---- epilogue: fold hi + lo/2048, write partials ----
    int g = lane >> 2, t4 = lane & 3;
#pragma unroll
    for (int mt = 0; mt < 2; mt++) {
        int row = r0 + wid * 32 + mt * 16 + g;
        float* d0 = outp + ((size_t)blockIdx.y * Mtot + row) * 8 + t4 * 2;
        float* d1 = outp + ((size_t)blockIdx.y * Mtot + row + 8) * 8 + t4 * 2;
        const float is = 1.f / 2048.f;
        *reinterpret_cast<float2*>(d0) = make_float2(
            c[mt][0][0] + c[mt][1][0] * is, c[mt][0][1] + c[mt][1][1] * is);
        *reinterpret_cast<float2*>(d1) = make_float2(
            c[mt][0][2] + c[mt][1][2] * is, c[mt][0][3] + c[mt][1][3] * is);
    }
}

// ---------------- r prep: r = sum(rpart) - meas -> hi/lo fp16 ----------------
__global__ void k_rprep(const float* __restrict__ meas) {
    int idx = blockIdx.x * blockDim.x + threadIdx.x;   // 32768
    int i = idx >> 3, b = idx & 7;
    float v = -meas[b * MM + i];
#pragma unroll
    for (int kc = 0; kc < KC1; kc++)
        v += g_rpart[((size_t)kc * MM + i) * 8 + b];
    __half hi = __float2half_rn(v);
    float  lo = (v - __half2float(hi)) * 2048.f;
    g_r16[(size_t)b * MM + i] = hi;
    g_r16[(size_t)(b + 8) * MM + i] = __float2half_rn(lo);
}

// ---------------- finish: x = t - grad ; xbar = 2x - xbar_old ----------------
__global__ void k_fin() {
    int idx = blockIdx.x * blockDim.x + threadIdx.x;
    if (idx >= BN) return;
    int b = idx >> 14;
    int j = idx & (NN - 1);
    float s = 0.f;
#pragma unroll
    for (int kc = 0; kc < KC2; kc++)
        s += g_gpart[((size_t)kc * NN + j) * 8 + b];
    float xn = g_t[idx] - s;
    float xbo = g_xbar[idx];
    g_x[idx] = xn;
    g_xbar[idx] = 2.f * xn - xbo;
}

// ---------------- output copy ----------------
__global__ void k_copy(float* __restrict__ out) {
    int idx = blockIdx.x * blockDim.x + threadIdx.x;
    if (idx < BN) out[idx] = g_x[idx];
}

// ---------------- launch ----------------
extern "C" void kernel_launch(void* const* d_in, const int* in_sizes, int n_in,
                              void* d_out, int out_size) {
    const float* meas = (const float*)d_in[0];
    const float* A    = (const float*)d_in[1];
    if (n_in >= 2 && in_sizes[0] != BB * MM) {
        meas = (const float*)d_in[1];
        A    = (const float*)d_in[0];
    }
    float* out = (float*)d_out;

    cudaFuncSetAttribute(k_mma, cudaFuncAttributeMaxDynamicSharedMemorySize, SM_TOTAL);

    k_setup<<<dim3(NN / 32, MM / 32), dim3(32, 8)>>>(A);
    k_zero<<<BN / 256, 256>>>();

    for (int it = 0; it < ITERS; it++) {
        int bi = it & 1;
        k_tv<<<BN / 256, 256>>>(bi);
        k_mma<<<dim3(MM / 128, KC1), 128, SM_TOTAL>>>(0);
        k_rprep<<<(MM * 8) / 256, 256>>>(meas);
        k_mma<<<dim3(NN / 128, KC2), 128, SM_TOTAL>>>(1);
        k_fin<<<BN / 256, 256>>>();
    }
    k_copy<<<BN / 256, 256>>>(out);
}